// round 2
// baseline (speedup 1.0000x reference)
#include <cuda_runtime.h>

// SPDNet on B200:
//   x:    [B,32,32] fp32 SPD   (B = 131072)
//   w1:   [32,4]
//   w3:   [4,4]
//   fc:   [16,2]
//   out:  logits [B,2] ++ feat [B,16]  (concatenated, fp32)
//
// Kernel 1: warp-per-sample bilinear  y = w1^T X w1  -> scratch [B,16]
// Kernel 2: thread-per-sample  ReEig(Jacobi) -> bilinear w3 -> LogEig(Jacobi) -> FC

#define BMAX 131072

// 8 MB scratch for the 4x4 intermediates (device-global: no allocation allowed)
__device__ float g_y[(size_t)BMAX * 16];

// ---------------------------------------------------------------------------
// Kernel 1: y = w1^T X w1 per sample, warp-per-sample.
// Coalesced global loads -> XOR-swizzled SMEM slab -> per-lane row GEMV ->
// symmetric 10-element warp butterfly reduction.
// ---------------------------------------------------------------------------
__global__ __launch_bounds__(256) void k1_bilinear(
    const float* __restrict__ x, const float* __restrict__ w1, int B)
{
    __shared__ float sx[8][1024];   // 8 warps * 32x32 floats (swizzled rows)
    __shared__ float w1s[128];      // w1 [32][4]

    const int tid  = threadIdx.x;
    const int warp = tid >> 5;
    const int lane = tid & 31;

    if (tid < 128) w1s[tid] = w1[tid];
    __syncthreads();

    const int s = blockIdx.x * 8 + warp;
    if (s >= B) return;

    // this lane's w1 row (row index == lane)
    const float4 wr = *(const float4*)&w1s[lane * 4];

    // --- coalesced load of the 4KB sample, swizzled store into SMEM ---
    const float4* __restrict__ xg = (const float4*)(x + (size_t)s * 1024);
    float* __restrict__ slab = sx[warp];
#pragma unroll
    for (int i = 0; i < 8; i++) {
        float4 v = xg[i * 32 + lane];
        int row = 4 * i + (lane >> 3);        // row this float4 belongs to
        int cg  = (lane & 7) ^ (row & 7);     // swizzled column-group
        *(float4*)&slab[row * 32 + 4 * cg] = v;
    }
    __syncwarp();

    // --- t = X[lane,:] @ w1   (lane r reads its own swizzled row) ---
    float t0 = 0.f, t1 = 0.f, t2 = 0.f, t3 = 0.f;
    const int r = lane;
#pragma unroll
    for (int c = 0; c < 8; c++) {
        float4 xv = *(const float4*)&slab[r * 32 + 4 * (c ^ (r & 7))];
        float4 wa = *(const float4*)&w1s[(4 * c + 0) * 4];
        float4 wb = *(const float4*)&w1s[(4 * c + 1) * 4];
        float4 wc = *(const float4*)&w1s[(4 * c + 2) * 4];
        float4 wd = *(const float4*)&w1s[(4 * c + 3) * 4];
        t0 += xv.x * wa.x + xv.y * wb.x + xv.z * wc.x + xv.w * wd.x;
        t1 += xv.x * wa.y + xv.y * wb.y + xv.z * wc.y + xv.w * wd.y;
        t2 += xv.x * wa.z + xv.y * wb.z + xv.z * wc.z + xv.w * wd.z;
        t3 += xv.x * wa.w + xv.y * wb.w + xv.z * wc.w + xv.w * wd.w;
    }

    // --- symmetric partials of y = w1^T t : 10 unique entries (j<=m) ---
    float p0 = wr.x * t0, p1 = wr.x * t1, p2 = wr.x * t2, p3 = wr.x * t3;
    float p4 = wr.y * t1, p5 = wr.y * t2, p6 = wr.y * t3;
    float p7 = wr.z * t2, p8 = wr.z * t3;
    float p9 = wr.w * t3;

#pragma unroll
    for (int off = 16; off > 0; off >>= 1) {
        p0 += __shfl_xor_sync(0xffffffffu, p0, off);
        p1 += __shfl_xor_sync(0xffffffffu, p1, off);
        p2 += __shfl_xor_sync(0xffffffffu, p2, off);
        p3 += __shfl_xor_sync(0xffffffffu, p3, off);
        p4 += __shfl_xor_sync(0xffffffffu, p4, off);
        p5 += __shfl_xor_sync(0xffffffffu, p5, off);
        p6 += __shfl_xor_sync(0xffffffffu, p6, off);
        p7 += __shfl_xor_sync(0xffffffffu, p7, off);
        p8 += __shfl_xor_sync(0xffffffffu, p8, off);
        p9 += __shfl_xor_sync(0xffffffffu, p9, off);
    }

    if (lane == 0) {
        float4* o = (float4*)&g_y[(size_t)s * 16];
        o[0] = make_float4(p0, p1, p2, p3);
        o[1] = make_float4(p1, p4, p5, p6);
        o[2] = make_float4(p2, p5, p7, p8);
        o[3] = make_float4(p3, p6, p8, p9);
    }
}

// ---------------------------------------------------------------------------
// Branchless 4x4 Jacobi eigensolver (fully unrolled, register resident)
// ---------------------------------------------------------------------------
__device__ __forceinline__ void jrot(float A[4][4], float V[4][4], int p, int q)
{
    const float apq = A[p][q];
    const float ha  = 0.5f * (A[q][q] - A[p][p]);
    const float rr  = sqrtf(ha * ha + apq * apq);
    const float t   = ((ha >= 0.f) ? apq : -apq) / (fabsf(ha) + rr + 1e-38f);
    const float c   = rsqrtf(1.f + t * t);
    const float s   = t * c;
#pragma unroll
    for (int k = 0; k < 4; k++) {           // column rotation
        float akp = A[k][p], akq = A[k][q];
        A[k][p] = c * akp - s * akq;
        A[k][q] = s * akp + c * akq;
    }
#pragma unroll
    for (int k = 0; k < 4; k++) {           // row rotation
        float apk = A[p][k], aqk = A[q][k];
        A[p][k] = c * apk - s * aqk;
        A[q][k] = s * apk + c * aqk;
    }
#pragma unroll
    for (int k = 0; k < 4; k++) {           // accumulate eigenvectors
        float vkp = V[k][p], vkq = V[k][q];
        V[k][p] = c * vkp - s * vkq;
        V[k][q] = s * vkp + c * vkq;
    }
}

__device__ __forceinline__ void jacobi4(float A[4][4], float V[4][4])
{
#pragma unroll
    for (int i = 0; i < 4; i++)
#pragma unroll
        for (int j = 0; j < 4; j++)
            V[i][j] = (i == j) ? 1.f : 0.f;

#pragma unroll
    for (int sweep = 0; sweep < 6; sweep++) {
        jrot(A, V, 0, 1);
        jrot(A, V, 0, 2);
        jrot(A, V, 0, 3);
        jrot(A, V, 1, 2);
        jrot(A, V, 1, 3);
        jrot(A, V, 2, 3);
    }
}

// M = V diag(lam) V^T
__device__ __forceinline__ void recon4(const float V[4][4], const float lam[4],
                                       float M[4][4])
{
    float G[4][4];
#pragma unroll
    for (int i = 0; i < 4; i++)
#pragma unroll
        for (int m = 0; m < 4; m++)
            G[i][m] = V[i][m] * lam[m];
#pragma unroll
    for (int i = 0; i < 4; i++)
#pragma unroll
        for (int j = 0; j < 4; j++) {
            float acc = 0.f;
#pragma unroll
            for (int m = 0; m < 4; m++) acc += G[i][m] * V[j][m];
            M[i][j] = acc;
        }
}

// ---------------------------------------------------------------------------
// Kernel 2: ReEig -> bilinear(w3) -> LogEig -> FC, thread-per-sample
// ---------------------------------------------------------------------------
__global__ __launch_bounds__(256) void k2_eig(
    const float* __restrict__ w3g, const float* __restrict__ fcg,
    float* __restrict__ outL, float* __restrict__ outF, int B)
{
    __shared__ float w3s[16];
    __shared__ float fcs[32];
    if (threadIdx.x < 16) w3s[threadIdx.x] = w3g[threadIdx.x];
    if (threadIdx.x < 32) fcs[threadIdx.x] = fcg[threadIdx.x];
    __syncthreads();

    const int s = blockIdx.x * blockDim.x + threadIdx.x;
    if (s >= B) return;

    // load y (4x4)
    float A[4][4];
    {
        const float4* yp = (const float4*)&g_y[(size_t)s * 16];
        float4 a0 = yp[0], a1 = yp[1], a2 = yp[2], a3 = yp[3];
        A[0][0] = a0.x; A[0][1] = a0.y; A[0][2] = a0.z; A[0][3] = a0.w;
        A[1][0] = a1.x; A[1][1] = a1.y; A[1][2] = a1.z; A[1][3] = a1.w;
        A[2][0] = a2.x; A[2][1] = a2.y; A[2][2] = a2.z; A[2][3] = a2.w;
        A[3][0] = a3.x; A[3][1] = a3.y; A[3][2] = a3.z; A[3][3] = a3.w;
    }

    // --- ReEig ---
    float V[4][4];
    jacobi4(A, V);
    float lam[4];
#pragma unroll
    for (int m = 0; m < 4; m++) lam[m] = fmaxf(A[m][m], 1e-4f);
    float x1[4][4];
    recon4(V, lam, x1);

    // --- bilinear w3:  Z = w3^T x1 w3 ---
    float tt[4][4];
#pragma unroll
    for (int i = 0; i < 4; i++)
#pragma unroll
        for (int b = 0; b < 4; b++) {
            float acc = 0.f;
#pragma unroll
            for (int k = 0; k < 4; k++) acc += x1[i][k] * w3s[k * 4 + b];
            tt[i][b] = acc;
        }
    float Z[4][4];
#pragma unroll
    for (int a = 0; a < 4; a++)
#pragma unroll
        for (int b = 0; b < 4; b++) {
            float acc = 0.f;
#pragma unroll
            for (int i = 0; i < 4; i++) acc += w3s[i * 4 + a] * tt[i][b];
            Z[a][b] = acc;
        }

    // --- LogEig ---
    float V2[4][4];
    jacobi4(Z, V2);
#pragma unroll
    for (int m = 0; m < 4; m++) lam[m] = logf(fmaxf(Z[m][m], 1e-10f));
    float x3[4][4];
    recon4(V2, lam, x3);

    // --- FC: logits = feat @ fc_w, fc_w is [16,2] row-major ---
    float l0 = 0.f, l1 = 0.f;
#pragma unroll
    for (int i = 0; i < 4; i++)
#pragma unroll
        for (int j = 0; j < 4; j++) {
            const int k = i * 4 + j;
            l0 += x3[i][j] * fcs[k * 2 + 0];
            l1 += x3[i][j] * fcs[k * 2 + 1];
        }

    if (outL) {
        float2* lp = (float2*)(outL + (size_t)s * 2);
        *lp = make_float2(l0, l1);
    }
    if (outF) {
        float4* fp = (float4*)(outF + (size_t)s * 16);
        fp[0] = make_float4(x3[0][0], x3[0][1], x3[0][2], x3[0][3]);
        fp[1] = make_float4(x3[1][0], x3[1][1], x3[1][2], x3[1][3]);
        fp[2] = make_float4(x3[2][0], x3[2][1], x3[2][2], x3[2][3]);
        fp[3] = make_float4(x3[3][0], x3[3][1], x3[3][2], x3[3][3]);
    }
}

// ---------------------------------------------------------------------------
extern "C" void kernel_launch(void* const* d_in, const int* in_sizes, int n_in,
                              void* d_out, int out_size)
{
    const float* x  = (const float*)d_in[0];
    const float* w1 = (const float*)d_in[1];
    const float* w3 = (const float*)d_in[2];
    const float* fc = (const float*)d_in[3];

    int B = in_sizes[0] / 1024;
    if (B > BMAX) B = BMAX;

    float* out  = (float*)d_out;
    float* outL = nullptr;
    float* outF = nullptr;
    if (out_size == 18 * B) {            // (logits, feat) concatenated
        outL = out;
        outF = out + (size_t)2 * B;
    } else if (out_size == 2 * B) {      // logits only
        outL = out;
    } else if (out_size == 16 * B) {     // feat only
        outF = out;
    } else {                             // fallback: assume (logits, feat)
        outL = out;
        if (out_size >= 18 * B) outF = out + (size_t)2 * B;
    }

    k1_bilinear<<<(B + 7) / 8, 256>>>(x, w1, B);
    k2_eig<<<(B + 255) / 256, 256>>>(w3, fc, outL, outF, B);
}

// round 4
// speedup vs baseline: 1.1717x; 1.1717x over previous
#include <cuda_runtime.h>

// SPDNet fused, B200 (sm_100a):
//   x:[B,32,32] fp32 SPD, w1:[32,4], w3:[4,4], fc:[16,2]
//   out: logits [B,2] ++ feat [B,16]
//
// One kernel. Per warp, alternating:
//   collect phase (x32): coalesced load of one 4KB sample (register-prefetched
//     one iteration ahead) -> swizzled SMEM slab -> per-lane row GEMV
//     t = X w1 -> 10 symmetric partials -> warp butterfly; lane L keeps
//     sample L's y in registers.
//   eig phase: all 32 lanes run an independent 4x4 Jacobi chain
//     (ReEig -> bilinear w3 -> LogEig -> FC) and write outputs.

#define TPB      128
#define NWARP    4
#define BATCHES  2
#define SPB      (NWARP * 32 * BATCHES)   // 256 samples per block

// ---------------- fast 4x4 Jacobi ----------------
__device__ __forceinline__ void jrot(float A[4][4], float V[4][4], int p, int q)
{
    const float apq = A[p][q];
    const float ha  = 0.5f * (A[q][q] - A[p][p]);
    const float r2  = ha * ha + apq * apq + 1e-30f;
    const float rr  = r2 * rsqrtf(r2);                       // |(ha,apq)|
    const float t   = __fdividef((ha >= 0.f) ? apq : -apq, fabsf(ha) + rr);
    const float c   = rsqrtf(1.f + t * t);
    const float s   = t * c;
#pragma unroll
    for (int k = 0; k < 4; k++) {
        float akp = A[k][p], akq = A[k][q];
        A[k][p] = c * akp - s * akq;
        A[k][q] = s * akp + c * akq;
    }
#pragma unroll
    for (int k = 0; k < 4; k++) {
        float apk = A[p][k], aqk = A[q][k];
        A[p][k] = c * apk - s * aqk;
        A[q][k] = s * apk + c * aqk;
    }
#pragma unroll
    for (int k = 0; k < 4; k++) {
        float vkp = V[k][p], vkq = V[k][q];
        V[k][p] = c * vkp - s * vkq;
        V[k][q] = s * vkp + c * vkq;
    }
}

__device__ __forceinline__ void jacobi4(float A[4][4], float V[4][4])
{
#pragma unroll
    for (int i = 0; i < 4; i++)
#pragma unroll
        for (int j = 0; j < 4; j++)
            V[i][j] = (i == j) ? 1.f : 0.f;
#pragma unroll
    for (int sweep = 0; sweep < 4; sweep++) {
        jrot(A, V, 0, 1);
        jrot(A, V, 0, 2);
        jrot(A, V, 0, 3);
        jrot(A, V, 1, 2);
        jrot(A, V, 1, 3);
        jrot(A, V, 2, 3);
    }
}

__device__ __forceinline__ void recon4(const float V[4][4], const float lam[4],
                                       float M[4][4])
{
    float G[4][4];
#pragma unroll
    for (int i = 0; i < 4; i++)
#pragma unroll
        for (int m = 0; m < 4; m++)
            G[i][m] = V[i][m] * lam[m];
#pragma unroll
    for (int i = 0; i < 4; i++)
#pragma unroll
        for (int j = 0; j < 4; j++) {
            float acc = 0.f;
#pragma unroll
            for (int m = 0; m < 4; m++) acc += G[i][m] * V[j][m];
            M[i][j] = acc;
        }
}

// ---------------- fused kernel ----------------
__global__ __launch_bounds__(TPB) void spdnet_fused(
    const float* __restrict__ x, const float* __restrict__ w1,
    const float* __restrict__ w3g, const float* __restrict__ fcg,
    float* __restrict__ outL, float* __restrict__ outF, int B)
{
    __shared__ float slab[NWARP][1024];   // per-warp 32x32 swizzled sample
    __shared__ float w1s[128];
    __shared__ float w3s[16];
    __shared__ float fcs[32];

    const int tid  = threadIdx.x;
    const int warp = tid >> 5;
    const int lane = tid & 31;

    w1s[tid] = w1[tid];                   // TPB == 128 exactly
    if (tid < 16) w3s[tid] = w3g[tid];
    if (tid < 32) fcs[tid] = fcg[tid];
    __syncthreads();

    const float4 wr = *(const float4*)&w1s[lane * 4];
    float* __restrict__ sl = slab[warp];
    const int blockBase = blockIdx.x * SPB;

    for (int b = 0; b < BATCHES; b++) {
        const int tileBase = blockBase + b * (NWARP * 32) + warp * 32;
        const int nIt = min(32, B - tileBase);   // samples this warp collects
        if (nIt <= 0) continue;

        // this lane will own sample (tileBase + lane)'s y in q0..q9
        float q0 = 0.f, q1 = 0.f, q2 = 0.f, q3 = 0.f, q4 = 0.f;
        float q5 = 0.f, q6 = 0.f, q7 = 0.f, q8 = 0.f, q9 = 0.f;

        // prefetch sample 0 into registers
        float4 pre[8];
        {
            const float4* __restrict__ xg =
                (const float4*)(x + (size_t)tileBase * 1024);
#pragma unroll
            for (int i = 0; i < 8; i++) pre[i] = xg[i * 32 + lane];
        }

        // ---------------- collect: nIt samples per warp ----------------
#pragma unroll 1
        for (int it = 0; it < nIt; ++it) {
            // store prefetched sample into swizzled SMEM
#pragma unroll
            for (int i = 0; i < 8; i++) {
                int row = 4 * i + (lane >> 3);
                int cg  = (lane & 7) ^ (row & 7);
                *(float4*)&sl[row * 32 + 4 * cg] = pre[i];
            }
            __syncwarp();

            // issue next sample's loads (overlap with GEMV + butterfly)
            if (it + 1 < nIt) {
                const float4* __restrict__ xg =
                    (const float4*)(x + (size_t)(tileBase + it + 1) * 1024);
#pragma unroll
                for (int i = 0; i < 8; i++) pre[i] = xg[i * 32 + lane];
            }

            // t = X[lane,:] @ w1
            float t0 = 0.f, t1 = 0.f, t2 = 0.f, t3 = 0.f;
            const int r = lane;
#pragma unroll
            for (int c = 0; c < 8; c++) {
                float4 xv = *(const float4*)&sl[r * 32 + 4 * (c ^ (r & 7))];
                float4 wa = *(const float4*)&w1s[(4 * c + 0) * 4];
                float4 wb = *(const float4*)&w1s[(4 * c + 1) * 4];
                float4 wc = *(const float4*)&w1s[(4 * c + 2) * 4];
                float4 wd = *(const float4*)&w1s[(4 * c + 3) * 4];
                t0 += xv.x * wa.x + xv.y * wb.x + xv.z * wc.x + xv.w * wd.x;
                t1 += xv.x * wa.y + xv.y * wb.y + xv.z * wc.y + xv.w * wd.y;
                t2 += xv.x * wa.z + xv.y * wb.z + xv.z * wc.z + xv.w * wd.z;
                t3 += xv.x * wa.w + xv.y * wb.w + xv.z * wc.w + xv.w * wd.w;
            }

            // 10 unique symmetric partials of y = w1^T t
            float p0 = wr.x * t0, p1 = wr.x * t1, p2 = wr.x * t2, p3 = wr.x * t3;
            float p4 = wr.y * t1, p5 = wr.y * t2, p6 = wr.y * t3;
            float p7 = wr.z * t2, p8 = wr.z * t3;
            float p9 = wr.w * t3;

#pragma unroll
            for (int off = 16; off > 0; off >>= 1) {
                p0 += __shfl_xor_sync(0xffffffffu, p0, off);
                p1 += __shfl_xor_sync(0xffffffffu, p1, off);
                p2 += __shfl_xor_sync(0xffffffffu, p2, off);
                p3 += __shfl_xor_sync(0xffffffffu, p3, off);
                p4 += __shfl_xor_sync(0xffffffffu, p4, off);
                p5 += __shfl_xor_sync(0xffffffffu, p5, off);
                p6 += __shfl_xor_sync(0xffffffffu, p6, off);
                p7 += __shfl_xor_sync(0xffffffffu, p7, off);
                p8 += __shfl_xor_sync(0xffffffffu, p8, off);
                p9 += __shfl_xor_sync(0xffffffffu, p9, off);
            }

            // butterfly leaves full sums on every lane; owner keeps them.
            // (the full-mask shfls also re-converge the warp, protecting
            //  the slab before next iteration's stores)
            if (lane == it) {
                q0 = p0; q1 = p1; q2 = p2; q3 = p3; q4 = p4;
                q5 = p5; q6 = p6; q7 = p7; q8 = p8; q9 = p9;
            }
        }

        // ---------------- eig: 32 independent samples ----------------
        const int g = tileBase + lane;
        if (g >= B) continue;

        float A[4][4];
        A[0][0] = q0; A[0][1] = q1; A[0][2] = q2; A[0][3] = q3;
        A[1][0] = q1; A[1][1] = q4; A[1][2] = q5; A[1][3] = q6;
        A[2][0] = q2; A[2][1] = q5; A[2][2] = q7; A[2][3] = q8;
        A[3][0] = q3; A[3][1] = q6; A[3][2] = q8; A[3][3] = q9;

        // ReEig
        float V[4][4];
        jacobi4(A, V);
        float lam[4];
#pragma unroll
        for (int m = 0; m < 4; m++) lam[m] = fmaxf(A[m][m], 1e-4f);
        float x1[4][4];
        recon4(V, lam, x1);

        // bilinear: Z = w3^T x1 w3
        float tt[4][4];
#pragma unroll
        for (int i = 0; i < 4; i++)
#pragma unroll
            for (int bb = 0; bb < 4; bb++) {
                float acc = 0.f;
#pragma unroll
                for (int k = 0; k < 4; k++) acc += x1[i][k] * w3s[k * 4 + bb];
                tt[i][bb] = acc;
            }
        float Z[4][4];
#pragma unroll
        for (int a = 0; a < 4; a++)
#pragma unroll
            for (int bb = 0; bb < 4; bb++) {
                float acc = 0.f;
#pragma unroll
                for (int i = 0; i < 4; i++) acc += w3s[i * 4 + a] * tt[i][bb];
                Z[a][bb] = acc;
            }

        // LogEig
        float V2[4][4];
        jacobi4(Z, V2);
#pragma unroll
        for (int m = 0; m < 4; m++) lam[m] = __logf(fmaxf(Z[m][m], 1e-10f));
        float x3[4][4];
        recon4(V2, lam, x3);

        // FC: logits = feat @ fc_w
        float l0 = 0.f, l1 = 0.f;
#pragma unroll
        for (int i = 0; i < 4; i++)
#pragma unroll
            for (int j = 0; j < 4; j++) {
                const int k = i * 4 + j;
                l0 += x3[i][j] * fcs[k * 2 + 0];
                l1 += x3[i][j] * fcs[k * 2 + 1];
            }

        if (outL) {
            *(float2*)(outL + (size_t)g * 2) = make_float2(l0, l1);
        }
        if (outF) {
            float4* fp = (float4*)(outF + (size_t)g * 16);
            fp[0] = make_float4(x3[0][0], x3[0][1], x3[0][2], x3[0][3]);
            fp[1] = make_float4(x3[1][0], x3[1][1], x3[1][2], x3[1][3]);
            fp[2] = make_float4(x3[2][0], x3[2][1], x3[2][2], x3[2][3]);
            fp[3] = make_float4(x3[3][0], x3[3][1], x3[3][2], x3[3][3]);
        }
    }
}

// ---------------------------------------------------------------------------
extern "C" void kernel_launch(void* const* d_in, const int* in_sizes, int n_in,
                              void* d_out, int out_size)
{
    const float* x  = (const float*)d_in[0];
    const float* w1 = (const float*)d_in[1];
    const float* w3 = (const float*)d_in[2];
    const float* fc = (const float*)d_in[3];

    const int B = in_sizes[0] / 1024;

    float* out  = (float*)d_out;
    float* outL = nullptr;
    float* outF = nullptr;
    if (out_size == 18 * B) {            // (logits, feat) concatenated
        outL = out;
        outF = out + (size_t)2 * B;
    } else if (out_size == 2 * B) {
        outL = out;
    } else if (out_size == 16 * B) {
        outF = out;
    } else {
        outL = out;
        if (out_size >= 18 * B) outF = out + (size_t)2 * B;
    }

    const int grid = (B + SPB - 1) / SPB;
    spdnet_fused<<<grid, TPB>>>(x, w1, w3, fc, outL, outF, B);
}

// round 7
// speedup vs baseline: 1.1757x; 1.0033x over previous
#include <cuda_runtime.h>

// SPDNet fused, B200 (sm_100a):
//   x:[B,32,32] fp32 SPD, w1:[32,4], w3:[4,4], fc:[16,2]
//   out: logits [B,2] ++ feat [B,16]
//
// One kernel, warp-per-32-samples (grid = B/128 = 1024 -> occupancy is
// residency-limited, not grid-limited):
//   collect (x32): coalesced LDG.128 (register-prefetched 1 ahead) ->
//     XOR-swizzled SMEM slab -> per-lane row GEMV (w1 broadcast from SMEM) ->
//     10 symmetric partials -> warp butterfly; lane L keeps sample L's y.
//   eig: 32 lanes run independent 4x4 Jacobi chains
//     (ReEig -> bilinear w3 -> LogEig -> FC).
//
// NOTE: no cudaMemcpyToSymbol* — legacy-stream ops break the harness's
// graph capture. All weights staged through SMEM inside the kernel.

#define TPB      128
#define NWARP    4
#define SPB      (NWARP * 32)   // 128 samples per block

// ---------------- fast 4x4 Jacobi ----------------
__device__ __forceinline__ void jrot(float A[4][4], float V[4][4], int p, int q)
{
    const float apq = A[p][q];
    const float ha  = 0.5f * (A[q][q] - A[p][p]);
    const float r2  = ha * ha + apq * apq + 1e-30f;
    const float rr  = r2 * rsqrtf(r2);                       // |(ha,apq)|
    const float t   = __fdividef((ha >= 0.f) ? apq : -apq, fabsf(ha) + rr);
    const float c   = rsqrtf(1.f + t * t);
    const float s   = t * c;
#pragma unroll
    for (int k = 0; k < 4; k++) {
        float akp = A[k][p], akq = A[k][q];
        A[k][p] = c * akp - s * akq;
        A[k][q] = s * akp + c * akq;
    }
#pragma unroll
    for (int k = 0; k < 4; k++) {
        float apk = A[p][k], aqk = A[q][k];
        A[p][k] = c * apk - s * aqk;
        A[q][k] = s * apk + c * aqk;
    }
#pragma unroll
    for (int k = 0; k < 4; k++) {
        float vkp = V[k][p], vkq = V[k][q];
        V[k][p] = c * vkp - s * vkq;
        V[k][q] = s * vkp + c * vkq;
    }
}

__device__ __forceinline__ void jacobi4(float A[4][4], float V[4][4])
{
#pragma unroll
    for (int i = 0; i < 4; i++)
#pragma unroll
        for (int j = 0; j < 4; j++)
            V[i][j] = (i == j) ? 1.f : 0.f;
#pragma unroll
    for (int sweep = 0; sweep < 4; sweep++) {
        jrot(A, V, 0, 1);
        jrot(A, V, 0, 2);
        jrot(A, V, 0, 3);
        jrot(A, V, 1, 2);
        jrot(A, V, 1, 3);
        jrot(A, V, 2, 3);
    }
}

__device__ __forceinline__ void recon4(const float V[4][4], const float lam[4],
                                       float M[4][4])
{
    float G[4][4];
#pragma unroll
    for (int i = 0; i < 4; i++)
#pragma unroll
        for (int m = 0; m < 4; m++)
            G[i][m] = V[i][m] * lam[m];
#pragma unroll
    for (int i = 0; i < 4; i++)
#pragma unroll
        for (int j = 0; j < 4; j++) {
            float acc = 0.f;
#pragma unroll
            for (int m = 0; m < 4; m++) acc += G[i][m] * V[j][m];
            M[i][j] = acc;
        }
}

// ---------------- fused kernel ----------------
__global__ __launch_bounds__(TPB) void spdnet_fused(
    const float* __restrict__ x, const float* __restrict__ w1,
    const float* __restrict__ w3g, const float* __restrict__ fcg,
    float* __restrict__ outL, float* __restrict__ outF, int B)
{
    __shared__ float slab[NWARP][1024];   // per-warp 32x32 swizzled sample
    __shared__ float w1s[128];
    __shared__ float w3s[16];
    __shared__ float fcs[32];

    const int tid  = threadIdx.x;
    const int warp = tid >> 5;
    const int lane = tid & 31;

    w1s[tid] = w1[tid];                   // TPB == 128 exactly
    if (tid < 16) w3s[tid] = w3g[tid];
    if (tid < 32) fcs[tid] = fcg[tid];
    __syncthreads();

    const float4 wr = *(const float4*)&w1s[lane * 4];
    float* __restrict__ sl = slab[warp];
    const int tileBase = blockIdx.x * SPB + warp * 32;
    const int nIt = min(32, B - tileBase);
    if (nIt <= 0) return;

    // lane will own sample (tileBase + lane)'s y in q0..q9
    float q0 = 0.f, q1 = 0.f, q2 = 0.f, q3 = 0.f, q4 = 0.f;
    float q5 = 0.f, q6 = 0.f, q7 = 0.f, q8 = 0.f, q9 = 0.f;

    // prefetch sample 0
    float4 pre[8];
    {
        const float4* __restrict__ xg = (const float4*)(x + (size_t)tileBase * 1024);
#pragma unroll
        for (int i = 0; i < 8; i++) pre[i] = xg[i * 32 + lane];
    }

    // ---------------- collect: nIt samples per warp ----------------
#pragma unroll 1
    for (int it = 0; it < nIt; ++it) {
        // store prefetched sample into swizzled SMEM
#pragma unroll
        for (int i = 0; i < 8; i++) {
            int row = 4 * i + (lane >> 3);
            int cg  = (lane & 7) ^ (row & 7);
            *(float4*)&sl[row * 32 + 4 * cg] = pre[i];
        }
        __syncwarp();

        // issue next sample's loads (overlap with GEMV + butterfly)
        if (it + 1 < nIt) {
            const float4* __restrict__ xg =
                (const float4*)(x + (size_t)(tileBase + it + 1) * 1024);
#pragma unroll
            for (int i = 0; i < 8; i++) pre[i] = xg[i * 32 + lane];
        }

        // t = X[lane,:] @ w1
        float t0 = 0.f, t1 = 0.f, t2 = 0.f, t3 = 0.f;
        const int r = lane;
#pragma unroll
        for (int c = 0; c < 8; c++) {
            float4 xv = *(const float4*)&sl[r * 32 + 4 * (c ^ (r & 7))];
            float4 wa = *(const float4*)&w1s[(4 * c + 0) * 4];
            float4 wb = *(const float4*)&w1s[(4 * c + 1) * 4];
            float4 wc = *(const float4*)&w1s[(4 * c + 2) * 4];
            float4 wd = *(const float4*)&w1s[(4 * c + 3) * 4];
            t0 += xv.x * wa.x + xv.y * wb.x + xv.z * wc.x + xv.w * wd.x;
            t1 += xv.x * wa.y + xv.y * wb.y + xv.z * wc.y + xv.w * wd.y;
            t2 += xv.x * wa.z + xv.y * wb.z + xv.z * wc.z + xv.w * wd.z;
            t3 += xv.x * wa.w + xv.y * wb.w + xv.z * wc.w + xv.w * wd.w;
        }

        // 10 unique symmetric partials of y = w1^T t
        float p0 = wr.x * t0, p1 = wr.x * t1, p2 = wr.x * t2, p3 = wr.x * t3;
        float p4 = wr.y * t1, p5 = wr.y * t2, p6 = wr.y * t3;
        float p7 = wr.z * t2, p8 = wr.z * t3;
        float p9 = wr.w * t3;

#pragma unroll
        for (int off = 16; off > 0; off >>= 1) {
            p0 += __shfl_xor_sync(0xffffffffu, p0, off);
            p1 += __shfl_xor_sync(0xffffffffu, p1, off);
            p2 += __shfl_xor_sync(0xffffffffu, p2, off);
            p3 += __shfl_xor_sync(0xffffffffu, p3, off);
            p4 += __shfl_xor_sync(0xffffffffu, p4, off);
            p5 += __shfl_xor_sync(0xffffffffu, p5, off);
            p6 += __shfl_xor_sync(0xffffffffu, p6, off);
            p7 += __shfl_xor_sync(0xffffffffu, p7, off);
            p8 += __shfl_xor_sync(0xffffffffu, p8, off);
            p9 += __shfl_xor_sync(0xffffffffu, p9, off);
        }

        // butterfly leaves full sums on every lane; owner keeps them
        if (lane == it) {
            q0 = p0; q1 = p1; q2 = p2; q3 = p3; q4 = p4;
            q5 = p5; q6 = p6; q7 = p7; q8 = p8; q9 = p9;
        }
    }

    // ---------------- eig: 32 independent samples ----------------
    const int g = tileBase + lane;
    if (g >= B) return;

    float A[4][4];
    A[0][0] = q0; A[0][1] = q1; A[0][2] = q2; A[0][3] = q3;
    A[1][0] = q1; A[1][1] = q4; A[1][2] = q5; A[1][3] = q6;
    A[2][0] = q2; A[2][1] = q5; A[2][2] = q7; A[2][3] = q8;
    A[3][0] = q3; A[3][1] = q6; A[3][2] = q8; A[3][3] = q9;

    // ReEig
    float V[4][4];
    jacobi4(A, V);
    float lam[4];
#pragma unroll
    for (int m = 0; m < 4; m++) lam[m] = fmaxf(A[m][m], 1e-4f);
    float x1[4][4];
    recon4(V, lam, x1);

    // bilinear: Z = w3^T x1 w3
    float tt[4][4];
#pragma unroll
    for (int i = 0; i < 4; i++)
#pragma unroll
        for (int bb = 0; bb < 4; bb++) {
            float acc = 0.f;
#pragma unroll
            for (int k = 0; k < 4; k++) acc += x1[i][k] * w3s[k * 4 + bb];
            tt[i][bb] = acc;
        }
    float Z[4][4];
#pragma unroll
    for (int a = 0; a < 4; a++)
#pragma unroll
        for (int bb = 0; bb < 4; bb++) {
            float acc = 0.f;
#pragma unroll
            for (int i = 0; i < 4; i++) acc += w3s[i * 4 + a] * tt[i][bb];
            Z[a][bb] = acc;
        }

    // LogEig
    float V2[4][4];
    jacobi4(Z, V2);
#pragma unroll
    for (int m = 0; m < 4; m++) lam[m] = __logf(fmaxf(Z[m][m], 1e-10f));
    float x3[4][4];
    recon4(V2, lam, x3);

    // FC: logits = feat @ fc_w
    float l0 = 0.f, l1 = 0.f;
#pragma unroll
    for (int i = 0; i < 4; i++)
#pragma unroll
        for (int j = 0; j < 4; j++) {
            const int k = i * 4 + j;
            l0 += x3[i][j] * fcs[k * 2 + 0];
            l1 += x3[i][j] * fcs[k * 2 + 1];
        }

    if (outL) {
        *(float2*)(outL + (size_t)g * 2) = make_float2(l0, l1);
    }
    if (outF) {
        float4* fp = (float4*)(outF + (size_t)g * 16);
        fp[0] = make_float4(x3[0][0], x3[0][1], x3[0][2], x3[0][3]);
        fp[1] = make_float4(x3[1][0], x3[1][1], x3[1][2], x3[1][3]);
        fp[2] = make_float4(x3[2][0], x3[2][1], x3[2][2], x3[2][3]);
        fp[3] = make_float4(x3[3][0], x3[3][1], x3[3][2], x3[3][3]);
    }
}

// ---------------------------------------------------------------------------
extern "C" void kernel_launch(void* const* d_in, const int* in_sizes, int n_in,
                              void* d_out, int out_size)
{
    const float* x  = (const float*)d_in[0];
    const float* w1 = (const float*)d_in[1];
    const float* w3 = (const float*)d_in[2];
    const float* fc = (const float*)d_in[3];

    const int B = in_sizes[0] / 1024;

    float* out  = (float*)d_out;
    float* outL = nullptr;
    float* outF = nullptr;
    if (out_size == 18 * B) {            // (logits, feat) concatenated
        outL = out;
        outF = out + (size_t)2 * B;
    } else if (out_size == 2 * B) {
        outL = out;
    } else if (out_size == 16 * B) {
        outF = out;
    } else {
        outL = out;
        if (out_size >= 18 * B) outF = out + (size_t)2 * B;
    }

    const int grid = (B + SPB - 1) / SPB;
    spdnet_fused<<<grid, TPB>>>(x, w1, w3, fc, outL, outF, B);
}

// round 8
// speedup vs baseline: 1.2469x; 1.0606x over previous
#include <cuda_runtime.h>
#include <cstdint>

// SPDNet fused, B200 (sm_100a):
//   x:[B,32,32] fp32 SPD, w1:[32,4], w3:[4,4], fc:[16,2]
//   out: logits [B,2] ++ feat [B,16]
//
// One kernel, warp-per-32-samples.
//   collect (x32): cp.async.cg (global->SMEM direct, L1-bypass, double-
//     buffered per warp) -> XOR-swizzled slab -> per-lane row GEMV ->
//     10 symmetric partials -> warp butterfly; lane L keeps sample L's y.
//   eig: 32 lanes run independent 4x4 Jacobi chains
//     (ReEig -> bilinear w3 -> LogEig -> FC).
// __launch_bounds__(128, 6): cap regs so 6 blocks (24 warps, 37.5%) reside.

#define TPB      128
#define NWARP    4
#define SPB      (NWARP * 32)   // 128 samples per block

// ---------------- cp.async helpers ----------------
__device__ __forceinline__ void cp_async16(uint32_t smem_addr, const void* gptr)
{
    asm volatile("cp.async.cg.shared.global [%0], [%1], 16;"
                 :: "r"(smem_addr), "l"(gptr) : "memory");
}
__device__ __forceinline__ void cp_commit()
{
    asm volatile("cp.async.commit_group;" ::: "memory");
}
template <int N>
__device__ __forceinline__ void cp_wait()
{
    asm volatile("cp.async.wait_group %0;" :: "n"(N) : "memory");
}

// ---------------- fast 4x4 Jacobi ----------------
__device__ __forceinline__ void jrot(float A[4][4], float V[4][4], int p, int q)
{
    const float apq = A[p][q];
    const float ha  = 0.5f * (A[q][q] - A[p][p]);
    const float r2  = ha * ha + apq * apq + 1e-30f;
    const float rr  = r2 * rsqrtf(r2);                       // |(ha,apq)|
    const float t   = __fdividef((ha >= 0.f) ? apq : -apq, fabsf(ha) + rr);
    const float c   = rsqrtf(1.f + t * t);
    const float s   = t * c;
#pragma unroll
    for (int k = 0; k < 4; k++) {
        float akp = A[k][p], akq = A[k][q];
        A[k][p] = c * akp - s * akq;
        A[k][q] = s * akp + c * akq;
    }
#pragma unroll
    for (int k = 0; k < 4; k++) {
        float apk = A[p][k], aqk = A[q][k];
        A[p][k] = c * apk - s * aqk;
        A[q][k] = s * apk + c * aqk;
    }
#pragma unroll
    for (int k = 0; k < 4; k++) {
        float vkp = V[k][p], vkq = V[k][q];
        V[k][p] = c * vkp - s * vkq;
        V[k][q] = s * vkp + c * vkq;
    }
}

__device__ __forceinline__ void jacobi4(float A[4][4], float V[4][4])
{
#pragma unroll
    for (int i = 0; i < 4; i++)
#pragma unroll
        for (int j = 0; j < 4; j++)
            V[i][j] = (i == j) ? 1.f : 0.f;
#pragma unroll
    for (int sweep = 0; sweep < 4; sweep++) {
        jrot(A, V, 0, 1);
        jrot(A, V, 0, 2);
        jrot(A, V, 0, 3);
        jrot(A, V, 1, 2);
        jrot(A, V, 1, 3);
        jrot(A, V, 2, 3);
    }
}

__device__ __forceinline__ void recon4(const float V[4][4], const float lam[4],
                                       float M[4][4])
{
    float G[4][4];
#pragma unroll
    for (int i = 0; i < 4; i++)
#pragma unroll
        for (int m = 0; m < 4; m++)
            G[i][m] = V[i][m] * lam[m];
#pragma unroll
    for (int i = 0; i < 4; i++)
#pragma unroll
        for (int j = 0; j < 4; j++) {
            float acc = 0.f;
#pragma unroll
            for (int m = 0; m < 4; m++) acc += G[i][m] * V[j][m];
            M[i][j] = acc;
        }
}

// ---------------- fused kernel ----------------
__global__ __launch_bounds__(TPB, 6) void spdnet_fused(
    const float* __restrict__ x, const float* __restrict__ w1,
    const float* __restrict__ w3g, const float* __restrict__ fcg,
    float* __restrict__ outL, float* __restrict__ outF, int B)
{
    __shared__ float slab[NWARP][2][1024];  // per-warp double-buffered sample
    __shared__ float w1s[128];
    __shared__ float w3s[16];
    __shared__ float fcs[32];

    const int tid  = threadIdx.x;
    const int warp = tid >> 5;
    const int lane = tid & 31;

    w1s[tid] = w1[tid];                   // TPB == 128 exactly
    if (tid < 16) w3s[tid] = w3g[tid];
    if (tid < 32) fcs[tid] = fcg[tid];
    __syncthreads();

    const float4 wr = *(const float4*)&w1s[lane * 4];
    const int tileBase = blockIdx.x * SPB + warp * 32;
    const int nIt = min(32, B - tileBase);
    if (nIt <= 0) return;

    // per-lane swizzled SMEM byte offsets for the 8 fragments (loop-invariant)
    uint32_t soff[8];
#pragma unroll
    for (int i = 0; i < 8; i++) {
        int row = 4 * i + (lane >> 3);
        int cg  = (lane & 7) ^ (row & 7);
        soff[i] = (uint32_t)((row * 32 + 4 * cg) * 4);
    }
    const uint32_t sb0 = (uint32_t)__cvta_generic_to_shared(&slab[warp][0][0]);
    const uint32_t sb1 = (uint32_t)__cvta_generic_to_shared(&slab[warp][1][0]);

    // lane will own sample (tileBase + lane)'s y in q0..q9
    float q0 = 0.f, q1 = 0.f, q2 = 0.f, q3 = 0.f, q4 = 0.f;
    float q5 = 0.f, q6 = 0.f, q7 = 0.f, q8 = 0.f, q9 = 0.f;

    // prime: DMA sample 0 into buffer 0
    {
        const char* g = (const char*)(x + (size_t)tileBase * 1024) + lane * 16;
#pragma unroll
        for (int i = 0; i < 8; i++) cp_async16(sb0 + soff[i], g + i * 512);
        cp_commit();
    }

    // ---------------- collect: nIt samples per warp ----------------
#pragma unroll 1
    for (int it = 0; it < nIt; ++it) {
        const uint32_t sbc = (it & 1) ? sb1 : sb0;

        // issue DMA for sample it+1 into the other buffer, then wait for it
        if (it + 1 < nIt) {
            const uint32_t sbn = (it & 1) ? sb0 : sb1;
            const char* g = (const char*)(x + (size_t)(tileBase + it + 1) * 1024)
                            + lane * 16;
#pragma unroll
            for (int i = 0; i < 8; i++) cp_async16(sbn + soff[i], g + i * 512);
            cp_commit();
            cp_wait<1>();    // sample 'it' complete (1 newer group in flight)
        } else {
            cp_wait<0>();    // last sample: drain everything
        }
        __syncwarp();

        const float* sl = (it & 1) ? &slab[warp][1][0] : &slab[warp][0][0];

        // t = X[lane,:] @ w1
        float t0 = 0.f, t1 = 0.f, t2 = 0.f, t3 = 0.f;
        const int r = lane;
#pragma unroll
        for (int c = 0; c < 8; c++) {
            float4 xv = *(const float4*)&sl[r * 32 + 4 * (c ^ (r & 7))];
            float4 wa = *(const float4*)&w1s[(4 * c + 0) * 4];
            float4 wb = *(const float4*)&w1s[(4 * c + 1) * 4];
            float4 wc = *(const float4*)&w1s[(4 * c + 2) * 4];
            float4 wd = *(const float4*)&w1s[(4 * c + 3) * 4];
            t0 += xv.x * wa.x + xv.y * wb.x + xv.z * wc.x + xv.w * wd.x;
            t1 += xv.x * wa.y + xv.y * wb.y + xv.z * wc.y + xv.w * wd.y;
            t2 += xv.x * wa.z + xv.y * wb.z + xv.z * wc.z + xv.w * wd.z;
            t3 += xv.x * wa.w + xv.y * wb.w + xv.z * wc.w + xv.w * wd.w;
        }

        // 10 unique symmetric partials of y = w1^T t
        float p0 = wr.x * t0, p1 = wr.x * t1, p2 = wr.x * t2, p3 = wr.x * t3;
        float p4 = wr.y * t1, p5 = wr.y * t2, p6 = wr.y * t3;
        float p7 = wr.z * t2, p8 = wr.z * t3;
        float p9 = wr.w * t3;

#pragma unroll
        for (int off = 16; off > 0; off >>= 1) {
            p0 += __shfl_xor_sync(0xffffffffu, p0, off);
            p1 += __shfl_xor_sync(0xffffffffu, p1, off);
            p2 += __shfl_xor_sync(0xffffffffu, p2, off);
            p3 += __shfl_xor_sync(0xffffffffu, p3, off);
            p4 += __shfl_xor_sync(0xffffffffu, p4, off);
            p5 += __shfl_xor_sync(0xffffffffu, p5, off);
            p6 += __shfl_xor_sync(0xffffffffu, p6, off);
            p7 += __shfl_xor_sync(0xffffffffu, p7, off);
            p8 += __shfl_xor_sync(0xffffffffu, p8, off);
            p9 += __shfl_xor_sync(0xffffffffu, p9, off);
        }

        // butterfly leaves full sums on every lane; owner keeps them
        if (lane == it) {
            q0 = p0; q1 = p1; q2 = p2; q3 = p3; q4 = p4;
            q5 = p5; q6 = p6; q7 = p7; q8 = p8; q9 = p9;
        }
    }

    // ---------------- eig: 32 independent samples ----------------
    const int g = tileBase + lane;
    if (g >= B) return;

    float A[4][4];
    A[0][0] = q0; A[0][1] = q1; A[0][2] = q2; A[0][3] = q3;
    A[1][0] = q1; A[1][1] = q4; A[1][2] = q5; A[1][3] = q6;
    A[2][0] = q2; A[2][1] = q5; A[2][2] = q7; A[2][3] = q8;
    A[3][0] = q3; A[3][1] = q6; A[3][2] = q8; A[3][3] = q9;

    // ReEig
    float V[4][4];
    jacobi4(A, V);
    float lam[4];
#pragma unroll
    for (int m = 0; m < 4; m++) lam[m] = fmaxf(A[m][m], 1e-4f);
    float x1[4][4];
    recon4(V, lam, x1);

    // bilinear: Z = w3^T x1 w3
    float tt[4][4];
#pragma unroll
    for (int i = 0; i < 4; i++)
#pragma unroll
        for (int bb = 0; bb < 4; bb++) {
            float acc = 0.f;
#pragma unroll
            for (int k = 0; k < 4; k++) acc += x1[i][k] * w3s[k * 4 + bb];
            tt[i][bb] = acc;
        }
    float Z[4][4];
#pragma unroll
    for (int a = 0; a < 4; a++)
#pragma unroll
        for (int bb = 0; bb < 4; bb++) {
            float acc = 0.f;
#pragma unroll
            for (int i = 0; i < 4; i++) acc += w3s[i * 4 + a] * tt[i][bb];
            Z[a][bb] = acc;
        }

    // LogEig
    float V2[4][4];
    jacobi4(Z, V2);
#pragma unroll
    for (int m = 0; m < 4; m++) lam[m] = __logf(fmaxf(Z[m][m], 1e-10f));
    float x3[4][4];
    recon4(V2, lam, x3);

    // FC: logits = feat @ fc_w
    float l0 = 0.f, l1 = 0.f;
#pragma unroll
    for (int i = 0; i < 4; i++)
#pragma unroll
        for (int j = 0; j < 4; j++) {
            const int k = i * 4 + j;
            l0 += x3[i][j] * fcs[k * 2 + 0];
            l1 += x3[i][j] * fcs[k * 2 + 1];
        }

    if (outL) {
        *(float2*)(outL + (size_t)g * 2) = make_float2(l0, l1);
    }
    if (outF) {
        float4* fp = (float4*)(outF + (size_t)g * 16);
        fp[0] = make_float4(x3[0][0], x3[0][1], x3[0][2], x3[0][3]);
        fp[1] = make_float4(x3[1][0], x3[1][1], x3[1][2], x3[1][3]);
        fp[2] = make_float4(x3[2][0], x3[2][1], x3[2][2], x3[2][3]);
        fp[3] = make_float4(x3[3][0], x3[3][1], x3[3][2], x3[3][3]);
    }
}

// ---------------------------------------------------------------------------
extern "C" void kernel_launch(void* const* d_in, const int* in_sizes, int n_in,
                              void* d_out, int out_size)
{
    const float* x  = (const float*)d_in[0];
    const float* w1 = (const float*)d_in[1];
    const float* w3 = (const float*)d_in[2];
    const float* fc = (const float*)d_in[3];

    const int B = in_sizes[0] / 1024;

    float* out  = (float*)d_out;
    float* outL = nullptr;
    float* outF = nullptr;
    if (out_size == 18 * B) {            // (logits, feat) concatenated
        outL = out;
        outF = out + (size_t)2 * B;
    } else if (out_size == 2 * B) {
        outL = out;
    } else if (out_size == 16 * B) {
        outF = out;
    } else {
        outL = out;
        if (out_size >= 18 * B) outF = out + (size_t)2 * B;
    }

    const int grid = (B + SPB - 1) / SPB;
    spdnet_fused<<<grid, TPB>>>(x, w1, w3, fc, outL, outF, B);
}

// round 10
// speedup vs baseline: 1.4189x; 1.1379x over previous
#include <cuda_runtime.h>
#include <cstdint>

// SPDNet fused, B200 (sm_100a):
//   x:[B,32,32] fp32 SPD, w1:[32,4], w3:[4,4], fc:[16,2]
//   out: logits [B,2] ++ feat [B,16]
//
// Persistent grid (148 SMs x 6 blocks = 888) -> no wave-quantization tail.
// Each warp loops over 32-sample tiles (tile = globalWarp + k*totalWarps):
//   collect (x32): cp.async.cg double-buffered global->SMEM (L1 bypass),
//     buffer parity carried across tiles; last iteration prefetches the NEXT
//     tile's first sample so the eig phase hides its DRAM latency.
//     XOR-swizzled slab -> per-lane row GEMV -> 10 symmetric partials ->
//     warp butterfly; lane L keeps sample L's 4x4 y in registers.
//   eig: 32 lanes run independent 4x4 Jacobi chains
//     (ReEig -> bilinear w3 -> LogEig -> FC).

#define TPB      128
#define NWARP    4
#define NBLOCKS  888            // 148 SMs * 6 resident blocks

// ---------------- cp.async helpers ----------------
__device__ __forceinline__ void cp_async16(uint32_t smem_addr, const void* gptr)
{
    asm volatile("cp.async.cg.shared.global [%0], [%1], 16;"
                 :: "r"(smem_addr), "l"(gptr) : "memory");
}
__device__ __forceinline__ void cp_commit()
{
    asm volatile("cp.async.commit_group;" ::: "memory");
}
template <int N>
__device__ __forceinline__ void cp_wait()
{
    asm volatile("cp.async.wait_group %0;" :: "n"(N) : "memory");
}

// ---------------- fast 4x4 Jacobi ----------------
__device__ __forceinline__ void jrot(float A[4][4], float V[4][4], int p, int q)
{
    const float apq = A[p][q];
    const float ha  = 0.5f * (A[q][q] - A[p][p]);
    const float r2  = ha * ha + apq * apq + 1e-30f;
    const float rr  = r2 * rsqrtf(r2);                       // |(ha,apq)|
    const float t   = __fdividef((ha >= 0.f) ? apq : -apq, fabsf(ha) + rr);
    const float c   = rsqrtf(1.f + t * t);
    const float s   = t * c;
#pragma unroll
    for (int k = 0; k < 4; k++) {
        float akp = A[k][p], akq = A[k][q];
        A[k][p] = c * akp - s * akq;
        A[k][q] = s * akp + c * akq;
    }
#pragma unroll
    for (int k = 0; k < 4; k++) {
        float apk = A[p][k], aqk = A[q][k];
        A[p][k] = c * apk - s * aqk;
        A[q][k] = s * apk + c * aqk;
    }
#pragma unroll
    for (int k = 0; k < 4; k++) {
        float vkp = V[k][p], vkq = V[k][q];
        V[k][p] = c * vkp - s * vkq;
        V[k][q] = s * vkp + c * vkq;
    }
}

__device__ __forceinline__ void jacobi4(float A[4][4], float V[4][4])
{
#pragma unroll
    for (int i = 0; i < 4; i++)
#pragma unroll
        for (int j = 0; j < 4; j++)
            V[i][j] = (i == j) ? 1.f : 0.f;
#pragma unroll
    for (int sweep = 0; sweep < 4; sweep++) {
        jrot(A, V, 0, 1);
        jrot(A, V, 0, 2);
        jrot(A, V, 0, 3);
        jrot(A, V, 1, 2);
        jrot(A, V, 1, 3);
        jrot(A, V, 2, 3);
    }
}

__device__ __forceinline__ void recon4(const float V[4][4], const float lam[4],
                                       float M[4][4])
{
    float G[4][4];
#pragma unroll
    for (int i = 0; i < 4; i++)
#pragma unroll
        for (int m = 0; m < 4; m++)
            G[i][m] = V[i][m] * lam[m];
#pragma unroll
    for (int i = 0; i < 4; i++)
#pragma unroll
        for (int j = 0; j < 4; j++) {
            float acc = 0.f;
#pragma unroll
            for (int m = 0; m < 4; m++) acc += G[i][m] * V[j][m];
            M[i][j] = acc;
        }
}

// ---------------- fused persistent kernel ----------------
__global__ __launch_bounds__(TPB, 6) void spdnet_fused(
    const float* __restrict__ x, const float* __restrict__ w1,
    const float* __restrict__ w3g, const float* __restrict__ fcg,
    float* __restrict__ outL, float* __restrict__ outF, int B)
{
    __shared__ float slab[NWARP][2][1024];  // per-warp double-buffered sample
    __shared__ float w1s[128];
    __shared__ float w3s[16];
    __shared__ float fcs[32];

    const int tid  = threadIdx.x;
    const int warp = tid >> 5;
    const int lane = tid & 31;

    w1s[tid] = w1[tid];                   // TPB == 128 exactly
    if (tid < 16) w3s[tid] = w3g[tid];
    if (tid < 32) fcs[tid] = fcg[tid];
    __syncthreads();

    const float4 wr = *(const float4*)&w1s[lane * 4];

    // per-lane swizzled SMEM byte offsets for the 8 fragments (loop-invariant)
    uint32_t soff[8];
#pragma unroll
    for (int i = 0; i < 8; i++) {
        int row = 4 * i + (lane >> 3);
        int cg  = (lane & 7) ^ (row & 7);
        soff[i] = (uint32_t)((row * 32 + 4 * cg) * 4);
    }
    uint32_t sb[2];
    sb[0] = (uint32_t)__cvta_generic_to_shared(&slab[warp][0][0]);
    sb[1] = (uint32_t)__cvta_generic_to_shared(&slab[warp][1][0]);

    const int gwarp   = blockIdx.x * NWARP + warp;
    const int nWarps  = gridDim.x * NWARP;
    const int nTiles  = (B + 31) >> 5;

    uint32_t par = 0;    // buffer that holds/receives the sample being processed

    // prime: first tile's sample 0
    if (gwarp < nTiles) {
        const int base0 = gwarp * 32;
        const char* g = (const char*)(x + (size_t)base0 * 1024) + lane * 16;
#pragma unroll
        for (int i = 0; i < 8; i++) cp_async16(sb[par] + soff[i], g + i * 512);
        cp_commit();
    }

#pragma unroll 1
    for (int tile = gwarp; tile < nTiles; tile += nWarps) {
        const int tileBase = tile * 32;
        const int nIt = min(32, B - tileBase);

        // lane will own sample (tileBase + lane)'s y in q0..q9
        float q0 = 0.f, q1 = 0.f, q2 = 0.f, q3 = 0.f, q4 = 0.f;
        float q5 = 0.f, q6 = 0.f, q7 = 0.f, q8 = 0.f, q9 = 0.f;

        // ---------------- collect ----------------
#pragma unroll 1
        for (int it = 0; it < nIt; ++it) {
            // next sample to prefetch: it+1 in this tile, else next tile's 0
            int nextS = (it + 1 < nIt) ? (tileBase + it + 1)
                                       : (tile + nWarps < nTiles ? (tile + nWarps) * 32
                                                                 : -1);
            if (nextS >= 0) {
                const char* g = (const char*)(x + (size_t)nextS * 1024) + lane * 16;
                const uint32_t sbn = sb[par ^ 1];
#pragma unroll
                for (int i = 0; i < 8; i++) cp_async16(sbn + soff[i], g + i * 512);
                cp_commit();
                cp_wait<1>();    // current sample's group complete
            } else {
                cp_wait<0>();    // very last sample overall
            }
            __syncwarp();

            const float* sl = &slab[warp][par][0];

            // t = X[lane,:] @ w1
            float t0 = 0.f, t1 = 0.f, t2 = 0.f, t3 = 0.f;
            const int r = lane;
#pragma unroll
            for (int c = 0; c < 8; c++) {
                float4 xv = *(const float4*)&sl[r * 32 + 4 * (c ^ (r & 7))];
                float4 wa = *(const float4*)&w1s[(4 * c + 0) * 4];
                float4 wb = *(const float4*)&w1s[(4 * c + 1) * 4];
                float4 wc = *(const float4*)&w1s[(4 * c + 2) * 4];
                float4 wd = *(const float4*)&w1s[(4 * c + 3) * 4];
                t0 += xv.x * wa.x + xv.y * wb.x + xv.z * wc.x + xv.w * wd.x;
                t1 += xv.x * wa.y + xv.y * wb.y + xv.z * wc.y + xv.w * wd.y;
                t2 += xv.x * wa.z + xv.y * wb.z + xv.z * wc.z + xv.w * wd.z;
                t3 += xv.x * wa.w + xv.y * wb.w + xv.z * wc.w + xv.w * wd.w;
            }

            // 10 unique symmetric partials of y = w1^T t
            float p0 = wr.x * t0, p1 = wr.x * t1, p2 = wr.x * t2, p3 = wr.x * t3;
            float p4 = wr.y * t1, p5 = wr.y * t2, p6 = wr.y * t3;
            float p7 = wr.z * t2, p8 = wr.z * t3;
            float p9 = wr.w * t3;

#pragma unroll
            for (int off = 16; off > 0; off >>= 1) {
                p0 += __shfl_xor_sync(0xffffffffu, p0, off);
                p1 += __shfl_xor_sync(0xffffffffu, p1, off);
                p2 += __shfl_xor_sync(0xffffffffu, p2, off);
                p3 += __shfl_xor_sync(0xffffffffu, p3, off);
                p4 += __shfl_xor_sync(0xffffffffu, p4, off);
                p5 += __shfl_xor_sync(0xffffffffu, p5, off);
                p6 += __shfl_xor_sync(0xffffffffu, p6, off);
                p7 += __shfl_xor_sync(0xffffffffu, p7, off);
                p8 += __shfl_xor_sync(0xffffffffu, p8, off);
                p9 += __shfl_xor_sync(0xffffffffu, p9, off);
            }

            // butterfly leaves full sums on every lane; owner keeps them
            if (lane == it) {
                q0 = p0; q1 = p1; q2 = p2; q3 = p3; q4 = p4;
                q5 = p5; q6 = p6; q7 = p7; q8 = p8; q9 = p9;
            }
            par ^= 1;
        }

        // ---------------- eig: 32 independent samples ----------------
        // (next tile's sample 0 DMA is in flight underneath this)
        const int g = tileBase + lane;
        if (g >= B) continue;

        float A[4][4];
        A[0][0] = q0; A[0][1] = q1; A[0][2] = q2; A[0][3] = q3;
        A[1][0] = q1; A[1][1] = q4; A[1][2] = q5; A[1][3] = q6;
        A[2][0] = q2; A[2][1] = q5; A[2][2] = q7; A[2][3] = q8;
        A[3][0] = q3; A[3][1] = q6; A[3][2] = q8; A[3][3] = q9;

        // ReEig
        float V[4][4];
        jacobi4(A, V);
        float lam[4];
#pragma unroll
        for (int m = 0; m < 4; m++) lam[m] = fmaxf(A[m][m], 1e-4f);
        float x1[4][4];
        recon4(V, lam, x1);

        // bilinear: Z = w3^T x1 w3
        float tt[4][4];
#pragma unroll
        for (int i = 0; i < 4; i++)
#pragma unroll
            for (int bb = 0; bb < 4; bb++) {
                float acc = 0.f;
#pragma unroll
                for (int k = 0; k < 4; k++) acc += x1[i][k] * w3s[k * 4 + bb];
                tt[i][bb] = acc;
            }
        float Z[4][4];
#pragma unroll
        for (int a = 0; a < 4; a++)
#pragma unroll
            for (int bb = 0; bb < 4; bb++) {
                float acc = 0.f;
#pragma unroll
                for (int i = 0; i < 4; i++) acc += w3s[i * 4 + a] * tt[i][bb];
                Z[a][bb] = acc;
            }

        // LogEig
        float V2[4][4];
        jacobi4(Z, V2);
#pragma unroll
        for (int m = 0; m < 4; m++) lam[m] = __logf(fmaxf(Z[m][m], 1e-10f));
        float x3[4][4];
        recon4(V2, lam, x3);

        // FC: logits = feat @ fc_w
        float l0 = 0.f, l1 = 0.f;
#pragma unroll
        for (int i = 0; i < 4; i++)
#pragma unroll
            for (int j = 0; j < 4; j++) {
                const int k = i * 4 + j;
                l0 += x3[i][j] * fcs[k * 2 + 0];
                l1 += x3[i][j] * fcs[k * 2 + 1];
            }

        if (outL) {
            *(float2*)(outL + (size_t)g * 2) = make_float2(l0, l1);
        }
        if (outF) {
            float4* fp = (float4*)(outF + (size_t)g * 16);
            fp[0] = make_float4(x3[0][0], x3[0][1], x3[0][2], x3[0][3]);
            fp[1] = make_float4(x3[1][0], x3[1][1], x3[1][2], x3[1][3]);
            fp[2] = make_float4(x3[2][0], x3[2][1], x3[2][2], x3[2][3]);
            fp[3] = make_float4(x3[3][0], x3[3][1], x3[3][2], x3[3][3]);
        }
    }
}

// ---------------------------------------------------------------------------
extern "C" void kernel_launch(void* const* d_in, const int* in_sizes, int n_in,
                              void* d_out, int out_size)
{
    const float* x  = (const float*)d_in[0];
    const float* w1 = (const float*)d_in[1];
    const float* w3 = (const float*)d_in[2];
    const float* fc = (const float*)d_in[3];

    const int B = in_sizes[0] / 1024;

    float* out  = (float*)d_out;
    float* outL = nullptr;
    float* outF = nullptr;
    if (out_size == 18 * B) {            // (logits, feat) concatenated
        outL = out;
        outF = out + (size_t)2 * B;
    } else if (out_size == 2 * B) {
        outL = out;
    } else if (out_size == 16 * B) {
        outF = out;
    } else {
        outL = out;
        if (out_size >= 18 * B) outF = out + (size_t)2 * B;
    }

    // persistent grid; cap by tile count for small B
    int grid = NBLOCKS;
    const int nTiles = (B + 31) / 32;
    const int maxBlocks = (nTiles + NWARP - 1) / NWARP;
    if (grid > maxBlocks) grid = maxBlocks;

    spdnet_fused<<<grid, TPB>>>(x, w1, w3, fc, outL, outF, B);
}

// round 15
// speedup vs baseline: 1.4418x; 1.0162x over previous
#include <cuda_runtime.h>
#include <cstdint>

// SPDNet fused, B200 (sm_100a):
//   x:[B,32,32] fp32 SPD, w1:[32,4], w3:[4,4], fc:[16,2]
//   out: logits [B,2] ++ feat [B,16]
//
// Persistent grid + atomic tile queue (init kernel zeroes the counter each
// launch -> deterministic, graph-capturable). Warp-per-32-sample tiles:
//   collect (x32): cp.async.cg double-buffered global->SMEM, cross-tile
//     prefetch; per-lane row GEMV t = X[lane,:] @ w1 -> STS t to SMEM.
//     NO cross-lane butterfly: every 8 samples, the warp batch-computes
//     y = w1^T t for 8 samples at once (lane 4s+j does row j of sample s),
//     then 16 shfl.idx redistribute rows to owner lanes.
//   eig: 32 lanes run independent 4x4 Jacobi chains
//     (ReEig -> bilinear w3 -> LogEig -> FC).

#define TPB      96
#define NWARP    3
#define NBLOCKS  888            // 148 SMs * 6 resident blocks

__device__ unsigned int g_tileCtr;

__global__ void init_ctr() { g_tileCtr = 0u; }

// ---------------- cp.async helpers ----------------
__device__ __forceinline__ void cp_async16(uint32_t smem_addr, const void* gptr)
{
    asm volatile("cp.async.cg.shared.global [%0], [%1], 16;"
                 :: "r"(smem_addr), "l"(gptr) : "memory");
}
__device__ __forceinline__ void cp_commit()
{
    asm volatile("cp.async.commit_group;" ::: "memory");
}
template <int N>
__device__ __forceinline__ void cp_wait()
{
    asm volatile("cp.async.wait_group %0;" :: "n"(N) : "memory");
}

// ---------------- fast 4x4 Jacobi ----------------
__device__ __forceinline__ void jrot(float A[4][4], float V[4][4], int p, int q)
{
    const float apq = A[p][q];
    const float ha  = 0.5f * (A[q][q] - A[p][p]);
    const float r2  = ha * ha + apq * apq + 1e-30f;
    const float rr  = r2 * rsqrtf(r2);                       // |(ha,apq)|
    const float t   = __fdividef((ha >= 0.f) ? apq : -apq, fabsf(ha) + rr);
    const float c   = rsqrtf(1.f + t * t);
    const float s   = t * c;
#pragma unroll
    for (int k = 0; k < 4; k++) {
        float akp = A[k][p], akq = A[k][q];
        A[k][p] = c * akp - s * akq;
        A[k][q] = s * akp + c * akq;
    }
#pragma unroll
    for (int k = 0; k < 4; k++) {
        float apk = A[p][k], aqk = A[q][k];
        A[p][k] = c * apk - s * aqk;
        A[q][k] = s * apk + c * aqk;
    }
#pragma unroll
    for (int k = 0; k < 4; k++) {
        float vkp = V[k][p], vkq = V[k][q];
        V[k][p] = c * vkp - s * vkq;
        V[k][q] = s * vkp + c * vkq;
    }
}

__device__ __forceinline__ void jacobi4(float A[4][4], float V[4][4])
{
#pragma unroll
    for (int i = 0; i < 4; i++)
#pragma unroll
        for (int j = 0; j < 4; j++)
            V[i][j] = (i == j) ? 1.f : 0.f;
#pragma unroll
    for (int sweep = 0; sweep < 4; sweep++) {
        jrot(A, V, 0, 1);
        jrot(A, V, 0, 2);
        jrot(A, V, 0, 3);
        jrot(A, V, 1, 2);
        jrot(A, V, 1, 3);
        jrot(A, V, 2, 3);
    }
}

__device__ __forceinline__ void recon4(const float V[4][4], const float lam[4],
                                       float M[4][4])
{
    float G[4][4];
#pragma unroll
    for (int i = 0; i < 4; i++)
#pragma unroll
        for (int m = 0; m < 4; m++)
            G[i][m] = V[i][m] * lam[m];
#pragma unroll
    for (int i = 0; i < 4; i++)
#pragma unroll
        for (int j = 0; j < 4; j++) {
            float acc = 0.f;
#pragma unroll
            for (int m = 0; m < 4; m++) acc += G[i][m] * V[j][m];
            M[i][j] = acc;
        }
}

// ---------------- fused persistent kernel ----------------
__global__ __launch_bounds__(TPB, 6) void spdnet_fused(
    const float* __restrict__ x, const float* __restrict__ w1,
    const float* __restrict__ w3g, const float* __restrict__ fcg,
    float* __restrict__ outL, float* __restrict__ outF, int B)
{
    __shared__ float slab[NWARP][2][1024];  // per-warp double-buffered sample
    __shared__ float tst[NWARP][8][132];    // staged t rows (132: pad vs banks)
    __shared__ float w1s[128];
    __shared__ float w3s[16];
    __shared__ float fcs[32];

    const int tid  = threadIdx.x;
    const int warp = tid >> 5;
    const int lane = tid & 31;

    w1s[tid] = w1[tid];                   // TPB == 96
    if (tid < 32) w1s[96 + tid] = w1[96 + tid];
    if (tid < 16) w3s[tid] = w3g[tid];
    if (tid < 32) fcs[tid] = fcg[tid];
    __syncthreads();

    // per-lane swizzled SMEM byte offsets for the 8 fragments (loop-invariant)
    uint32_t soff[8];
#pragma unroll
    for (int i = 0; i < 8; i++) {
        int row = 4 * i + (lane >> 3);
        int cg  = (lane & 7) ^ (row & 7);
        soff[i] = (uint32_t)((row * 32 + 4 * cg) * 4);
    }
    uint32_t sb[2];
    sb[0] = (uint32_t)__cvta_generic_to_shared(&slab[warp][0][0]);
    sb[1] = (uint32_t)__cvta_generic_to_shared(&slab[warp][1][0]);

    const unsigned nTiles = (unsigned)((B + 31) >> 5);

    // grab first tile from the queue
    unsigned tile;
    if (lane == 0) tile = atomicAdd(&g_tileCtr, 1u);
    tile = __shfl_sync(0xffffffffu, tile, 0);

    uint32_t par = 0;

    // prime: first tile's sample 0
    if (tile < nTiles) {
        const char* g = (const char*)(x + (size_t)tile * 32 * 1024) + lane * 16;
#pragma unroll
        for (int i = 0; i < 8; i++) cp_async16(sb[par] + soff[i], g + i * 512);
        cp_commit();
    }

    while (tile < nTiles) {
        const int tileBase = (int)tile * 32;
        const int nIt = min(32, B - tileBase);

        float A[4][4];                 // filled batch-by-batch
        unsigned nextTile = 0xffffffffu;

        // ---------------- collect ----------------
#pragma unroll 1
        for (int it = 0; it < nIt; ++it) {
            // grab the next tile early so the atomic latency is hidden
            if (it == ((nIt >= 2) ? nIt - 2 : 0)) {
                unsigned nt;
                if (lane == 0) nt = atomicAdd(&g_tileCtr, 1u);
                nextTile = __shfl_sync(0xffffffffu, nt, 0);
            }

            // next sample to prefetch: it+1 here, else next tile's sample 0
            long long nextS = (it + 1 < nIt)
                              ? (long long)(tileBase + it + 1)
                              : ((nextTile < nTiles) ? (long long)nextTile * 32
                                                     : -1LL);
            if (nextS >= 0) {
                const char* g = (const char*)(x + (size_t)nextS * 1024) + lane * 16;
                const uint32_t sbn = sb[par ^ 1];
#pragma unroll
                for (int i = 0; i < 8; i++) cp_async16(sbn + soff[i], g + i * 512);
                cp_commit();
                cp_wait<1>();    // current sample's group complete
            } else {
                cp_wait<0>();    // very last sample overall
            }
            __syncwarp();

            const float* sl = &slab[warp][par][0];

            // t = X[lane,:] @ w1
            float t0 = 0.f, t1 = 0.f, t2 = 0.f, t3 = 0.f;
            const int r = lane;
#pragma unroll
            for (int c = 0; c < 8; c++) {
                float4 xv = *(const float4*)&sl[r * 32 + 4 * (c ^ (r & 7))];
                float4 wa = *(const float4*)&w1s[(4 * c + 0) * 4];
                float4 wb = *(const float4*)&w1s[(4 * c + 1) * 4];
                float4 wc = *(const float4*)&w1s[(4 * c + 2) * 4];
                float4 wd = *(const float4*)&w1s[(4 * c + 3) * 4];
                t0 += xv.x * wa.x + xv.y * wb.x + xv.z * wc.x + xv.w * wd.x;
                t1 += xv.x * wa.y + xv.y * wb.y + xv.z * wc.y + xv.w * wd.y;
                t2 += xv.x * wa.z + xv.y * wb.z + xv.z * wc.z + xv.w * wd.z;
                t3 += xv.x * wa.w + xv.y * wb.w + xv.z * wc.w + xv.w * wd.w;
            }

            // stage t row (no butterfly)
            *(float4*)&tst[warp][it & 7][lane << 2] = make_float4(t0, t1, t2, t3);

            // batch y-computation every 8 samples (or at tile tail)
            if ((it & 7) == 7 || it == nIt - 1) {
                __syncwarp();
                const int bt = it >> 3;
                const int sp = lane >> 2;          // batch sample this lane serves
                const int j  = lane & 3;           // y row this lane computes
                const float* tb = &tst[warp][sp][0];
                float ax = 0.f, ay = 0.f, az = 0.f, aw = 0.f;
#pragma unroll
                for (int rr2 = 0; rr2 < 32; rr2++) {
                    float4 t4 = *(const float4*)&tb[rr2 * 4];
                    float wjr = w1s[rr2 * 4 + j];
                    ax += wjr * t4.x; ay += wjr * t4.y;
                    az += wjr * t4.z; aw += wjr * t4.w;
                }
                // redistribute rows to owner lanes (owners = lanes 8bt..8bt+7)
                const int so = lane & 7;
#pragma unroll
                for (int jj = 0; jj < 4; jj++) {
                    const int src = 4 * so + jj;
                    float v0 = __shfl_sync(0xffffffffu, ax, src);
                    float v1 = __shfl_sync(0xffffffffu, ay, src);
                    float v2 = __shfl_sync(0xffffffffu, az, src);
                    float v3 = __shfl_sync(0xffffffffu, aw, src);
                    if ((lane >> 3) == bt) {
                        A[jj][0] = v0; A[jj][1] = v1;
                        A[jj][2] = v2; A[jj][3] = v3;
                    }
                }
                __syncwarp();   // tstore reusable next batch
            }

            par ^= 1;
        }

        // ---------------- eig: 32 independent samples ----------------
        const int g = tileBase + lane;
        if (g < B) {
            // symmetrize (y is symmetric analytically; enforce numerically)
#pragma unroll
            for (int p = 0; p < 4; p++)
#pragma unroll
                for (int q = 0; q < 4; q++) {
                    if (p < q) {
                        float v = 0.5f * (A[p][q] + A[q][p]);
                        A[p][q] = v; A[q][p] = v;
                    }
                }

            // ReEig
            float V[4][4];
            jacobi4(A, V);
            float lam[4];
#pragma unroll
            for (int m = 0; m < 4; m++) lam[m] = fmaxf(A[m][m], 1e-4f);
            float x1[4][4];
            recon4(V, lam, x1);

            // bilinear: Z = w3^T x1 w3
            float tt[4][4];
#pragma unroll
            for (int i = 0; i < 4; i++)
#pragma unroll
                for (int bb = 0; bb < 4; bb++) {
                    float acc = 0.f;
#pragma unroll
                    for (int k = 0; k < 4; k++) acc += x1[i][k] * w3s[k * 4 + bb];
                    tt[i][bb] = acc;
                }
            float Z[4][4];
#pragma unroll
            for (int a = 0; a < 4; a++)
#pragma unroll
                for (int bb = 0; bb < 4; bb++) {
                    float acc = 0.f;
#pragma unroll
                    for (int i = 0; i < 4; i++) acc += w3s[i * 4 + a] * tt[i][bb];
                    Z[a][bb] = acc;
                }

            // LogEig
            float V2[4][4];
            jacobi4(Z, V2);
#pragma unroll
            for (int m = 0; m < 4; m++) lam[m] = __logf(fmaxf(Z[m][m], 1e-10f));
            float x3[4][4];
            recon4(V2, lam, x3);

            // FC: logits = feat @ fc_w
            float l0 = 0.f, l1 = 0.f;
#pragma unroll
            for (int i = 0; i < 4; i++)
#pragma unroll
                for (int jq = 0; jq < 4; jq++) {
                    const int k = i * 4 + jq;
                    l0 += x3[i][jq] * fcs[k * 2 + 0];
                    l1 += x3[i][jq] * fcs[k * 2 + 1];
                }

            if (outL) {
                *(float2*)(outL + (size_t)g * 2) = make_float2(l0, l1);
            }
            if (outF) {
                float4* fp = (float4*)(outF + (size_t)g * 16);
                fp[0] = make_float4(x3[0][0], x3[0][1], x3[0][2], x3[0][3]);
                fp[1] = make_float4(x3[1][0], x3[1][1], x3[1][2], x3[1][3]);
                fp[2] = make_float4(x3[2][0], x3[2][1], x3[2][2], x3[2][3]);
                fp[3] = make_float4(x3[3][0], x3[3][1], x3[3][2], x3[3][3]);
            }
        }

        tile = nextTile;
    }
}

// ---------------------------------------------------------------------------
extern "C" void kernel_launch(void* const* d_in, const int* in_sizes, int n_in,
                              void* d_out, int out_size)
{
    const float* x  = (const float*)d_in[0];
    const float* w1 = (const float*)d_in[1];
    const float* w3 = (const float*)d_in[2];
    const float* fc = (const float*)d_in[3];

    const int B = in_sizes[0] / 1024;

    float* out  = (float*)d_out;
    float* outL = nullptr;
    float* outF = nullptr;
    if (out_size == 18 * B) {            // (logits, feat) concatenated
        outL = out;
        outF = out + (size_t)2 * B;
    } else if (out_size == 2 * B) {
        outL = out;
    } else if (out_size == 16 * B) {
        outF = out;
    } else {
        outL = out;
        if (out_size >= 18 * B) outF = out + (size_t)2 * B;
    }

    init_ctr<<<1, 1>>>();
    spdnet_fused<<<NBLOCKS, TPB>>>(x, w1, w3, fc, outL, outF, B);
}